// round 3
// baseline (speedup 1.0000x reference)
#include <cuda_runtime.h>
#include <cuda_bf16.h>

#define BINS 10
#define TPB 256
#define WARPS (TPB / 32)
#define NBLOCKS (148 * 8)

// Global scratch (no allocations allowed): per-bin accumulators.
__device__ double g_sum[BINS];
__device__ double g_cnt[BINS];

__global__ void ghmc_zero_kernel() {
    int i = threadIdx.x;
    if (i < BINS) { g_sum[i] = 0.0; g_cnt[i] = 0.0; }
}

// softplus(z) for z in (0,1):
// ln(1+e^z) = ln2 + z/2 + z^2/8 - z^4/192 + z^6/2880 - 17 z^8/645120
// max abs err ~2e-6 on [0,1]; pure FMA.
__device__ __forceinline__ float softplus01(float z) {
    float u = z * z;
    float p = fmaf(-2.6351690e-5f, u, 3.4722222e-4f);
    p = fmaf(p, u, -5.2083335e-3f);
    p = fmaf(p, u, 0.125f);
    p = p * u;
    return fmaf(0.5f, z, 0.69314718f) + p;
}

__global__ void __launch_bounds__(TPB)
ghmc_main_kernel(const float* __restrict__ pred,
                 const int* __restrict__ target,
                 long long n) {
    // Per-warp, per-lane private histogram slots: bank index == lane -> conflict-free.
    __shared__ float s_sum[WARPS][BINS][32];
    __shared__ float s_cnt[WARPS][BINS][32];

    const int tid  = threadIdx.x;
    const int lane = tid & 31;
    const int warp = tid >> 5;

    // Zero shared accumulators.
    {
        float* a = &s_sum[0][0][0];
        float* b = &s_cnt[0][0][0];
        for (int i = tid; i < WARPS * BINS * 32; i += TPB) { a[i] = 0.0f; b[i] = 0.0f; }
    }
    __syncthreads();

    const long long stride = (long long)gridDim.x * TPB;
    const long long gtid   = (long long)blockIdx.x * TPB + tid;

    // Vectorized main loop: float4 / int4 (N = 20,971,520 is divisible by 4).
    const long long nv = n >> 2;
    const float4* p4 = (const float4*)pred;
    const int4*   t4 = (const int4*)target;

    for (long long i = gtid; i < nv; i += stride) {
        float4 p = p4[i];
        int4   t = t4[i];
        #pragma unroll
        for (int k = 0; k < 4; ++k) {
            float pk = (k == 0) ? p.x : (k == 1) ? p.y : (k == 2) ? p.z : p.w;
            int   tk = (k == 0) ? t.x : (k == 1) ? t.y : (k == 2) ? t.z : t.w;

            float e  = __expf(-pk);                      // MUFU.EX2 + FMUL
            float z  = __fdividef(1.0f, 1.0f + e);       // MUFU.RCP
            float tf = (float)tk;
            float g  = fabsf(z - tf);                    // |sigmoid(p) - t|
            int idx  = min(__float2int_rz(g * 10.0f), BINS - 1);
            float bce = fmaf(-tf, z, softplus01(z));     // softplus(z) - t*z

            s_sum[warp][idx][lane] += bce;
            s_cnt[warp][idx][lane] += 1.0f;
        }
    }

    // Scalar tail (defensive; empty for this shape).
    for (long long i = (nv << 2) + gtid; i < n; i += stride) {
        float pk = pred[i];
        int   tk = target[i];
        float e  = __expf(-pk);
        float z  = __fdividef(1.0f, 1.0f + e);
        float tf = (float)tk;
        float g  = fabsf(z - tf);
        int idx  = min(__float2int_rz(g * 10.0f), BINS - 1);
        float bce = fmaf(-tf, z, softplus01(z));
        s_sum[warp][idx][lane] += bce;
        s_cnt[warp][idx][lane] += 1.0f;
    }

    __syncthreads();

    // Block reduction: warp w handles bins w, w+WARPS, ...
    for (int b = warp; b < BINS; b += WARPS) {
        float vs = 0.0f, vc = 0.0f;
        #pragma unroll
        for (int w = 0; w < WARPS; ++w) {
            vs += s_sum[w][b][lane];
            vc += s_cnt[w][b][lane];
        }
        #pragma unroll
        for (int o = 16; o > 0; o >>= 1) {
            vs += __shfl_xor_sync(0xFFFFFFFFu, vs, o);
            vc += __shfl_xor_sync(0xFFFFFFFFu, vc, o);
        }
        if (lane == 0) {
            atomicAdd(&g_sum[b], (double)vs);
            atomicAdd(&g_cnt[b], (double)vc);
        }
    }
}

__global__ void ghmc_finalize_kernel(float* __restrict__ out) {
    if (threadIdx.x != 0) return;
    double acc = 0.0, nn = 0.0;
    #pragma unroll
    for (int b = 0; b < BINS; ++b) {
        double c = g_cnt[b];
        if (c > 0.0) { nn += 1.0; acc += g_sum[b] / c; }
    }
    if (nn < 1.0) nn = 1.0;
    out[0] = (float)(acc / nn);
}

extern "C" void kernel_launch(void* const* d_in, const int* in_sizes, int n_in,
                              void* d_out, int out_size) {
    const float* pred   = (const float*)d_in[0];
    const int*   target = (const int*)d_in[1];
    float*       out    = (float*)d_out;
    long long n = (long long)in_sizes[0];

    ghmc_zero_kernel<<<1, 32>>>();
    ghmc_main_kernel<<<NBLOCKS, TPB>>>(pred, target, n);
    ghmc_finalize_kernel<<<1, 32>>>(out);
}

// round 4
// speedup vs baseline: 1.0399x; 1.0399x over previous
#include <cuda_runtime.h>
#include <cuda_bf16.h>

#define BINS 10
#define TPB 256
#define WARPS (TPB / 32)
#define NBLOCKS (148 * 6)   // exactly one wave at occupancy 6 (pinned by launch_bounds)

// Global scratch (no allocations allowed): per-bin accumulators + completion ticket.
// Self-resetting: the last block finalizes, writes out, and zeroes everything so
// every graph replay starts from identical state.
__device__ double g_sum[BINS];
__device__ double g_cnt[BINS];
__device__ unsigned int g_ticket;

// softplus(z) for z in (0,1):
// ln(1+e^z) = ln2 + z/2 + z^2/8 - z^4/192 + z^6/2880 - 17 z^8/645120
// max abs err ~2e-6 on [0,1]; pure FMA.
__device__ __forceinline__ float softplus01(float z) {
    float u = z * z;
    float p = fmaf(-2.6351690e-5f, u, 3.4722222e-4f);
    p = fmaf(p, u, -5.2083335e-3f);
    p = fmaf(p, u, 0.125f);
    p = p * u;
    return fmaf(0.5f, z, 0.69314718f) + p;
}

// sigmoid(x) = 0.5 + 0.5*tanh(x/2): FMUL + MUFU.TANH + FMA (1 MUFU vs 2 for exp+rcp)
__device__ __forceinline__ float sigmoid_fast(float x) {
    float h = 0.5f * x;
    float th;
    asm("tanh.approx.f32 %0, %1;" : "=f"(th) : "f"(h));
    return fmaf(0.5f, th, 0.5f);
}

// One element: bin + accumulate into per-warp-per-lane float2 {bce_sum, count} slot.
// Slot layout s[warp][bin][lane] (float2): bank = f(lane) only -> conflict-free LDS.64/STS.64.
__device__ __forceinline__ void proc(float pk, int tk, float2* __restrict__ base) {
    float z  = sigmoid_fast(pk);
    float tf = (float)tk;
    float g  = fabsf(z - tf);
    int idx  = min(__float2int_rz(g * 10.0f), BINS - 1);
    float bce = fmaf(-tf, z, softplus01(z));
    float2* p = base + idx * 32;
    float2 v = *p;
    v.x += bce;
    v.y += 1.0f;
    *p = v;
}

__global__ void __launch_bounds__(TPB, 6)
ghmc_fused_kernel(const float* __restrict__ pred,
                  const int* __restrict__ target,
                  float* __restrict__ out,
                  long long n) {
    __shared__ float2 s_acc[WARPS][BINS][32];   // 20,480 B
    __shared__ float s_bs[BINS], s_bc[BINS];

    const int tid  = threadIdx.x;
    const int lane = tid & 31;
    const int warp = tid >> 5;

    // Zero shared accumulators.
    {
        float2* a = &s_acc[0][0][0];
        for (int i = tid; i < WARPS * BINS * 32; i += TPB) a[i] = make_float2(0.0f, 0.0f);
    }
    __syncthreads();

    float2* base = &s_acc[warp][0][lane];

    const long long stride = (long long)gridDim.x * TPB;
    const long long gtid   = (long long)blockIdx.x * TPB + tid;

    // Vectorized loop: float4/int4, unrolled x2 over grid stride (4 LDG.128 in flight).
    const long long nv = n >> 2;
    const float4* p4 = (const float4*)pred;
    const int4*   t4 = (const int4*)target;

    long long i = gtid;
    for (; i + stride < nv; i += 2 * stride) {
        float4 pa = p4[i];
        int4   ta = t4[i];
        float4 pb = p4[i + stride];
        int4   tb = t4[i + stride];
        proc(pa.x, ta.x, base); proc(pa.y, ta.y, base);
        proc(pa.z, ta.z, base); proc(pa.w, ta.w, base);
        proc(pb.x, tb.x, base); proc(pb.y, tb.y, base);
        proc(pb.z, tb.z, base); proc(pb.w, tb.w, base);
    }
    if (i < nv) {
        float4 pa = p4[i];
        int4   ta = t4[i];
        proc(pa.x, ta.x, base); proc(pa.y, ta.y, base);
        proc(pa.z, ta.z, base); proc(pa.w, ta.w, base);
    }
    // Scalar tail (empty for this shape; defensive).
    for (long long j = (nv << 2) + gtid; j < n; j += stride)
        proc(pred[j], target[j], base);

    __syncthreads();

    // Block reduction: warp w handles bins w, w+WARPS, ...
    for (int b = warp; b < BINS; b += WARPS) {
        float vs = 0.0f, vc = 0.0f;
        #pragma unroll
        for (int w = 0; w < WARPS; ++w) {
            float2 v = s_acc[w][b][lane];
            vs += v.x;
            vc += v.y;
        }
        #pragma unroll
        for (int o = 16; o > 0; o >>= 1) {
            vs += __shfl_xor_sync(0xFFFFFFFFu, vs, o);
            vc += __shfl_xor_sync(0xFFFFFFFFu, vc, o);
        }
        if (lane == 0) { s_bs[b] = vs; s_bc[b] = vc; }
    }
    __syncthreads();

    // Thread 0 only: global atomics -> fence -> ticket (textbook ordering).
    if (tid == 0) {
        #pragma unroll
        for (int b = 0; b < BINS; ++b) {
            atomicAdd(&g_sum[b], (double)s_bs[b]);
            atomicAdd(&g_cnt[b], (double)s_bc[b]);
        }
        __threadfence();
        unsigned t = atomicAdd(&g_ticket, 1u);
        if (t == gridDim.x - 1) {
            __threadfence();
            // loss = ( sum_{b: cnt>0} S_b / cnt_b ) / n_nonempty   (tot cancels)
            double acc = 0.0, nn = 0.0;
            #pragma unroll
            for (int b = 0; b < BINS; ++b) {
                double c = atomicAdd(&g_cnt[b], 0.0);   // L2-coherent read
                double s = atomicAdd(&g_sum[b], 0.0);
                if (c > 0.0) { nn += 1.0; acc += s / c; }
            }
            if (nn < 1.0) nn = 1.0;
            out[0] = (float)(acc / nn);
            // Reset state for the next graph replay.
            #pragma unroll
            for (int b = 0; b < BINS; ++b) { g_sum[b] = 0.0; g_cnt[b] = 0.0; }
            g_ticket = 0u;
        }
    }
}

extern "C" void kernel_launch(void* const* d_in, const int* in_sizes, int n_in,
                              void* d_out, int out_size) {
    const float* pred   = (const float*)d_in[0];
    const int*   target = (const int*)d_in[1];
    float*       out    = (float*)d_out;
    long long n = (long long)in_sizes[0];

    ghmc_fused_kernel<<<NBLOCKS, TPB>>>(pred, target, out, n);
}